// round 2
// baseline (speedup 1.0000x reference)
#include <cuda_runtime.h>
#include <cuda_bf16.h>
#include <math_constants.h>

// ============================================================================
// HVIN (hierarchical value-iteration network), fully fused.
//   k_compose : precompose (W_r o W_h) -> WC (border-exact) and W5 (5x5 fast path)
//   k_main    : one block per image; entire pipeline in shared memory
//   k_epi     : BN finalize (double-precision stat combine) + dueling heads
// ============================================================================

#define N_IMG 128
#define KVI   16

// ---------------- device scratch (no allocations allowed) -------------------
__device__ float g_WCf[162];            // fine  WC[j(9)][ci(2)][i(9)]
__device__ float g_WCc[162];            // coarse
__device__ float g_W5f[50];             // fine  W5[ci(2)][5x5]
__device__ float g_W5c[50];             // coarse
__device__ float g_partial[N_IMG * 20]; // per image: [c] sum, [10+c] sumsq
__device__ float g_qout[N_IMG * 10];    // q gathered at (S1, S2)

// ---------------- shared memory layout for k_main (float offsets) -----------
#define SM_WQF 0        // 4320  conv_q_ws    (16,10,3,3,3)
#define SM_WQC 4320     // 2880  vi_conv_q_ws (16,10,2,3,3)
#define SM_WCF 7200     // 162
#define SM_WCC 7362     // 162
#define SM_W5F 7524     // 50
#define SM_W5C 7574     // 50
#define SM_X   7624     // 2*68*68 = 9248   X, pad-2 zero ring
#define SM_X1  16872    // 2*36*36 = 2592   pooled X, pad-2 zero ring
#define SM_R1  19464    // 34*34 = 1156     coarse r1, pad-1
#define SM_VA  20620    // 1156             coarse v buffer A, pad-1
#define SM_VB  21776    // 1156             coarse v buffer B
#define SM_SC  22932    // 1024             coarse s (32x32)
#define SM_RF  23956    // 2*66*66 = 8712   fine [m, r], pad-1
#define SM_VFA 32668    // 4356             fine v buffer A, pad-1
#define SM_VFB 37024    // 4356             fine v buffer B
#define SM_SF  41380    // 4096             fine s (64x64)
#define SM_RED 45476    // 320              BN block-reduce scratch
#define SM_TOT 45796
#define SMEM_BYTES (SM_TOT * 4)

// ============================================================================
// k_compose
//   WC[lvl][(jy*3+jx)*18 + ci*9 + iy*3+ix] = sum_o wr[o][j] * wh[o][ci][i]
//   W5[lvl][ci*25 + f] = sum_{j,i : j+i = f} WC   (f in 5x5, offset f-2)
// lvl 0 = fine (conv_h_w/conv_r_w), lvl 1 = coarse (vi_conv_h_w/vi_conv_r_w).
// ============================================================================
__global__ void k_compose(const float* __restrict__ wh_f, const float* __restrict__ wr_f,
                          const float* __restrict__ wh_c, const float* __restrict__ wr_c) {
    __shared__ float sWC[2][162];
    const int t = threadIdx.x;
    for (int idx = t; idx < 324; idx += 256) {
        int lvl = idx / 162, rem = idx % 162;
        int j = rem / 18, ci = (rem % 18) / 9, i = rem % 9;
        const float* wr = lvl ? wr_c : wr_f;
        const float* wh = lvl ? wh_c : wh_f;
        float acc = 0.f;
        for (int o = 0; o < 150; o++)
            acc = fmaf(wr[o * 9 + j], wh[(o * 2 + ci) * 9 + i], acc);
        sWC[lvl][rem] = acc;
        (lvl ? g_WCc : g_WCf)[rem] = acc;
    }
    __syncthreads();
    for (int idx = t; idx < 100; idx += 256) {
        int lvl = idx / 50, rem = idx % 50;
        int ci = rem / 25, f = rem % 25, fy = f / 5, fx = f % 5;
        float acc = 0.f;
        for (int jy = 0; jy < 3; jy++)
            for (int jx = 0; jx < 3; jx++) {
                int iy = fy - jy, ix = fx - jx;
                if (iy >= 0 && iy <= 2 && ix >= 0 && ix <= 2)
                    acc += sWC[lvl][(jy * 3 + jx) * 18 + ci * 9 + iy * 3 + ix];
            }
        (lvl ? g_W5c : g_W5f)[rem] = acc;
    }
}

// ============================================================================
// Fused r front-end: r = conv_r(conv_h(X)) with SAME padding at both stages.
// Interior pixels: exact 5x5 composed conv (W5) on zero-padded X.
// Border pixels: WC form with the clipped-h inside test (bit-exact semantics).
//   sxb points at a pad-2 channel-major image; H = image size; ROW = padded row;
//   CHS = padded channel stride.
// ============================================================================
template <int H, int ROW, int CHS>
__device__ __forceinline__ float rfront(const float* __restrict__ sxb,
                                        const float* __restrict__ w5,
                                        const float* __restrict__ wc,
                                        int y, int x) {
    float acc = 0.f;
    if (y >= 1 && y <= H - 2 && x >= 1 && x <= H - 2) {
#pragma unroll
        for (int ci = 0; ci < 2; ci++) {
            const float* xb = &sxb[ci * CHS + y * ROW + x];  // (y-2)+pad2 row
#pragma unroll
            for (int fy = 0; fy < 5; fy++)
#pragma unroll
                for (int fx = 0; fx < 5; fx++)
                    acc = fmaf(w5[ci * 25 + fy * 5 + fx], xb[fy * ROW + fx], acc);
        }
    } else {
#pragma unroll
        for (int jy = 0; jy < 3; jy++)
#pragma unroll
            for (int jx = 0; jx < 3; jx++) {
                int py = y + jy - 1, px = x + jx - 1;
                if (py >= 0 && py < H && px >= 0 && px < H) {
                    const float* wcj = &wc[(jy * 3 + jx) * 18];
#pragma unroll
                    for (int ci = 0; ci < 2; ci++) {
                        const float* xb = &sxb[ci * CHS + (py + 1) * ROW + (px + 1)];
#pragma unroll
                        for (int iy = 0; iy < 3; iy++)
#pragma unroll
                            for (int ix = 0; ix < 3; ix++)
                                acc = fmaf(wcj[ci * 9 + iy * 3 + ix], xb[iy * ROW + ix], acc);
                    }
                }
            }
    }
    return acc;
}

// ============================================================================
// k_main: one block = one image.
// ============================================================================
__global__ __launch_bounds__(512) void k_main(const float* __restrict__ X,
                                              const int* __restrict__ S1,
                                              const int* __restrict__ S2,
                                              const float* __restrict__ wqf,
                                              const float* __restrict__ wqc) {
    extern __shared__ float sm[];
    const int t = threadIdx.x;
    const int n = blockIdx.x;

    // ---- stage weights + zero work buffers -------------------------------
    for (int i = t; i < 4320; i += 512) sm[SM_WQF + i] = wqf[i];
    for (int i = t; i < 2880; i += 512) sm[SM_WQC + i] = wqc[i];
    if (t < 162) { sm[SM_WCF + t] = g_WCf[t]; sm[SM_WCC + t] = g_WCc[t]; }
    if (t < 50)  { sm[SM_W5F + t] = g_W5f[t]; sm[SM_W5C + t] = g_W5c[t]; }
    for (int i = SM_X + t; i < SM_RED; i += 512) sm[i] = 0.f;
    __syncthreads();

    // ---- load X into pad-2 smem ------------------------------------------
    for (int i = t; i < 8192; i += 512) {
        int ci = i >> 12, y = (i >> 6) & 63, x = i & 63;
        sm[SM_X + ci * 4624 + (y + 2) * 68 + (x + 2)] = X[n * 8192 + i];
    }
    __syncthreads();

    // ---- maxpool 2x2 -> X1 (pad-2) ---------------------------------------
    for (int i = t; i < 2048; i += 512) {
        int ci = i >> 10, y = (i >> 5) & 31, x = i & 31;
        const float* b = &sm[SM_X + ci * 4624 + (2 * y + 2) * 68 + (2 * x + 2)];
        float v = fmaxf(fmaxf(b[0], b[1]), fmaxf(b[68], b[69]));
        sm[SM_X1 + ci * 1296 + (y + 2) * 36 + (x + 2)] = v;
    }
    __syncthreads();

    // ---- coarse r1 = (vi_conv_r o vi_conv_h)(X1) -------------------------
    for (int i = t; i < 1024; i += 512) {
        int y = i >> 5, x = i & 31;
        sm[SM_R1 + (y + 1) * 34 + (x + 1)] =
            rfront<32, 36, 1296>(&sm[SM_X1], &sm[SM_W5C], &sm[SM_WCC], y, x);
    }
    __syncthreads();

    // ---- coarse VI loop (16 iters, 2-ch in, 10-ch out, max, accumulate) --
    {
        float* vcc = sm + SM_VA;
        float* vcn = sm + SM_VB;
#pragma unroll 1
        for (int k = 0; k < KVI; k++) {
            if (t < 256) {
                int y = t >> 3, x0 = (t & 7) * 4;
                float pin[2][3][6];
#pragma unroll
                for (int r = 0; r < 3; r++)
#pragma unroll
                    for (int cc = 0; cc < 6; cc++) {
                        pin[0][r][cc] = sm[SM_R1 + (y + r) * 34 + x0 + cc];
                        pin[1][r][cc] = vcc[(y + r) * 34 + x0 + cc];
                    }
                float v0 = -CUDART_INF_F, v1 = v0, v2 = v0, v3 = v0;
#pragma unroll 2
                for (int c = 0; c < 10; c++) {
                    const float* w = &sm[SM_WQC + ((k * 10 + c) * 2) * 9];
                    float a0 = 0.f, a1 = 0.f, a2 = 0.f, a3 = 0.f;
#pragma unroll
                    for (int cin = 0; cin < 2; cin++)
#pragma unroll
                        for (int r = 0; r < 3; r++)
#pragma unroll
                            for (int s = 0; s < 3; s++) {
                                float wv = w[cin * 9 + r * 3 + s];
                                a0 = fmaf(wv, pin[cin][r][s + 0], a0);
                                a1 = fmaf(wv, pin[cin][r][s + 1], a1);
                                a2 = fmaf(wv, pin[cin][r][s + 2], a2);
                                a3 = fmaf(wv, pin[cin][r][s + 3], a3);
                            }
                    v0 = fmaxf(v0, a0); v1 = fmaxf(v1, a1);
                    v2 = fmaxf(v2, a2); v3 = fmaxf(v3, a3);
                }
                vcn[(y + 1) * 34 + x0 + 1] = v0;
                vcn[(y + 1) * 34 + x0 + 2] = v1;
                vcn[(y + 1) * 34 + x0 + 3] = v2;
                vcn[(y + 1) * 34 + x0 + 4] = v3;
                sm[SM_SC + y * 32 + x0 + 0] += v0;
                sm[SM_SC + y * 32 + x0 + 1] += v1;
                sm[SM_SC + y * 32 + x0 + 2] += v2;
                sm[SM_SC + y * 32 + x0 + 3] += v3;
            }
            __syncthreads();
            float* tmp = vcc; vcc = vcn; vcn = tmp;
        }
    }

    // ---- upsample v1 = s/4 (jax linear, half-pixel, edge-renorm == clamp) -
    //      -> fine ch0 (m); and fine r -> fine ch1
    for (int i = t; i < 4096; i += 512) {
        int oy = i >> 6, ox = i & 63;
        int ty = oy >> 1, tx = ox >> 1;
        int ya, yb, xa, xb;
        float wya, wyb, wxa, wxb;
        if ((oy & 1) == 0) { ya = (ty > 0) ? ty - 1 : 0; yb = ty; wya = 0.25f; wyb = 0.75f; }
        else               { ya = ty; yb = (ty < 31) ? ty + 1 : 31; wya = 0.75f; wyb = 0.25f; }
        if ((ox & 1) == 0) { xa = (tx > 0) ? tx - 1 : 0; xb = tx; wxa = 0.25f; wxb = 0.75f; }
        else               { xa = tx; xb = (tx < 31) ? tx + 1 : 31; wxa = 0.75f; wxb = 0.25f; }
        float v = wya * (wxa * sm[SM_SC + ya * 32 + xa] + wxb * sm[SM_SC + ya * 32 + xb]) +
                  wyb * (wxa * sm[SM_SC + yb * 32 + xa] + wxb * sm[SM_SC + yb * 32 + xb]);
        sm[SM_RF + (oy + 1) * 66 + (ox + 1)] = v * 0.25f;  // /4 denom folded in
    }
    for (int i = t; i < 4096; i += 512) {
        int y = i >> 6, x = i & 63;
        sm[SM_RF + 4356 + (y + 1) * 66 + (x + 1)] =
            rfront<64, 68, 4624>(&sm[SM_X], &sm[SM_W5F], &sm[SM_WCF], y, x);
    }
    __syncthreads();

    // ---- fine VI loop (16 iters, 3-ch in) --------------------------------
    float* vfc = sm + SM_VFA;
    float* vfn = sm + SM_VFB;
#pragma unroll 1
    for (int k = 0; k < KVI; k++) {
#pragma unroll 1
        for (int rep = 0; rep < 2; rep++) {
            int gid = t + rep * 512;
            int y = gid >> 4, x0 = (gid & 15) * 4;
            float pin[3][3][6];
#pragma unroll
            for (int r = 0; r < 3; r++)
#pragma unroll
                for (int cc = 0; cc < 6; cc++) {
                    pin[0][r][cc] = sm[SM_RF + (y + r) * 66 + x0 + cc];
                    pin[1][r][cc] = sm[SM_RF + 4356 + (y + r) * 66 + x0 + cc];
                    pin[2][r][cc] = vfc[(y + r) * 66 + x0 + cc];
                }
            float v0 = -CUDART_INF_F, v1 = v0, v2 = v0, v3 = v0;
#pragma unroll 2
            for (int c = 0; c < 10; c++) {
                const float* w = &sm[SM_WQF + ((k * 10 + c) * 3) * 9];
                float a0 = 0.f, a1 = 0.f, a2 = 0.f, a3 = 0.f;
#pragma unroll
                for (int cin = 0; cin < 3; cin++)
#pragma unroll
                    for (int r = 0; r < 3; r++)
#pragma unroll
                        for (int s = 0; s < 3; s++) {
                            float wv = w[cin * 9 + r * 3 + s];
                            a0 = fmaf(wv, pin[cin][r][s + 0], a0);
                            a1 = fmaf(wv, pin[cin][r][s + 1], a1);
                            a2 = fmaf(wv, pin[cin][r][s + 2], a2);
                            a3 = fmaf(wv, pin[cin][r][s + 3], a3);
                        }
                v0 = fmaxf(v0, a0); v1 = fmaxf(v1, a1);
                v2 = fmaxf(v2, a2); v3 = fmaxf(v3, a3);
            }
            vfn[(y + 1) * 66 + x0 + 1] = v0;
            vfn[(y + 1) * 66 + x0 + 2] = v1;
            vfn[(y + 1) * 66 + x0 + 3] = v2;
            vfn[(y + 1) * 66 + x0 + 4] = v3;
            sm[SM_SF + y * 64 + x0 + 0] += v0;
            sm[SM_SF + y * 64 + x0 + 1] += v1;
            sm[SM_SF + y * 64 + x0 + 2] += v2;
            sm[SM_SF + y * 64 + x0 + 3] += v3;
        }
        __syncthreads();
        float* tmp = vfc; vfc = vfn; vfn = tmp;
    }

    // ---- vbar = s/16 into the current v buffer (ring still zero) ---------
    for (int i = t; i < 4096; i += 512) {
        int y = i >> 6, x = i & 63;
        vfc[(y + 1) * 66 + (x + 1)] = sm[SM_SF + i] * (1.f / 16.f);
    }
    __syncthreads();

    // ---- final q = conv([m, r, vbar], wqf[15]); BN partials; gather ------
    float psum[10], psq[10];
#pragma unroll
    for (int c = 0; c < 10; c++) { psum[c] = 0.f; psq[c] = 0.f; }
    const int s1 = S1[n], s2 = S2[n];
#pragma unroll 1
    for (int rep = 0; rep < 2; rep++) {
        int gid = t + rep * 512;
        int y = gid >> 4, x0 = (gid & 15) * 4;
        float pin[3][3][6];
#pragma unroll
        for (int r = 0; r < 3; r++)
#pragma unroll
            for (int cc = 0; cc < 6; cc++) {
                pin[0][r][cc] = sm[SM_RF + (y + r) * 66 + x0 + cc];
                pin[1][r][cc] = sm[SM_RF + 4356 + (y + r) * 66 + x0 + cc];
                pin[2][r][cc] = vfc[(y + r) * 66 + x0 + cc];
            }
        bool gy = (y == s1) && (s2 >= x0) && (s2 < x0 + 4);
#pragma unroll 2
        for (int c = 0; c < 10; c++) {
            const float* w = &sm[SM_WQF + ((15 * 10 + c) * 3) * 9];
            float a0 = 0.f, a1 = 0.f, a2 = 0.f, a3 = 0.f;
#pragma unroll
            for (int cin = 0; cin < 3; cin++)
#pragma unroll
                for (int r = 0; r < 3; r++)
#pragma unroll
                    for (int s = 0; s < 3; s++) {
                        float wv = w[cin * 9 + r * 3 + s];
                        a0 = fmaf(wv, pin[cin][r][s + 0], a0);
                        a1 = fmaf(wv, pin[cin][r][s + 1], a1);
                        a2 = fmaf(wv, pin[cin][r][s + 2], a2);
                        a3 = fmaf(wv, pin[cin][r][s + 3], a3);
                    }
            psum[c] += (a0 + a1) + (a2 + a3);
            psq[c] += (a0 * a0 + a1 * a1) + (a2 * a2 + a3 * a3);
            if (gy) {
                int d = s2 - x0;
                float qv = (d == 0) ? a0 : (d == 1) ? a1 : (d == 2) ? a2 : a3;
                g_qout[n * 10 + c] = qv;
            }
        }
    }

    // ---- block-reduce BN partials ----------------------------------------
    int lane = t & 31, wid = t >> 5;
#pragma unroll
    for (int c = 0; c < 10; c++) {
        float s = psum[c], q = psq[c];
#pragma unroll
        for (int o = 16; o > 0; o >>= 1) {
            s += __shfl_down_sync(0xffffffffu, s, o);
            q += __shfl_down_sync(0xffffffffu, q, o);
        }
        if (lane == 0) {
            sm[SM_RED + wid * 20 + c] = s;
            sm[SM_RED + wid * 20 + 10 + c] = q;
        }
    }
    __syncthreads();
    if (t < 20) {
        float s = 0.f;
        for (int w = 0; w < 16; w++) s += sm[SM_RED + w * 20 + t];
        g_partial[n * 20 + t] = s;
    }
}

// ============================================================================
// k_epi: BN finalize + dueling heads. 1 block, 128 threads (one per image).
// ============================================================================
__global__ void k_epi(const float* __restrict__ gamma, const float* __restrict__ beta,
                      const float* __restrict__ w1, const float* __restrict__ w2,
                      float* __restrict__ out) {
    __shared__ float sMean[10], sScale[10], sBeta[10];
    int t = threadIdx.x;
    if (t < 10) {
        double s = 0.0, sq = 0.0;
        for (int nn = 0; nn < N_IMG; nn++) {
            s += (double)g_partial[nn * 20 + t];
            sq += (double)g_partial[nn * 20 + 10 + t];
        }
        double cnt = (double)N_IMG * 4096.0;
        double mu = s / cnt;
        double var = sq / cnt - mu * mu;
        sMean[t] = (float)mu;
        sScale[t] = (float)((double)gamma[t] / sqrt(var + 1e-5));
        sBeta[t] = beta[t];
    }
    __syncthreads();

    float qn[10];
#pragma unroll
    for (int c = 0; c < 10; c++)
        qn[c] = (g_qout[t * 10 + c] - sMean[c]) * sScale[c] + sBeta[c];
    float a = 0.f;
#pragma unroll
    for (int c = 0; c < 10; c++) a += qn[c] * w1[c];
    a = fmaxf(a, 0.f);
    float b[8], bm = 0.f;
#pragma unroll
    for (int j = 0; j < 8; j++) {
        float bb = 0.f;
#pragma unroll
        for (int c = 0; c < 10; c++) bb += qn[c] * w2[j * 10 + c];
        bb = fmaxf(bb, 0.f);
        b[j] = bb;
        bm += bb;
    }
    bm *= 0.125f;
#pragma unroll
    for (int j = 0; j < 8; j++) out[t * 8 + j] = a + b[j] - bm;
}

// ============================================================================
extern "C" void kernel_launch(void* const* d_in, const int* in_sizes, int n_in,
                              void* d_out, int out_size) {
    const float* X    = (const float*)d_in[0];
    const int*   S1   = (const int*)d_in[1];
    const int*   S2   = (const int*)d_in[2];
    const float* whf  = (const float*)d_in[3];   // conv_h_w (150,2,3,3)
    const float* wrf  = (const float*)d_in[4];   // conv_r_w (1,150,3,3)
    const float* wqf  = (const float*)d_in[5];   // conv_q_ws (16,10,3,3,3)
    const float* gam  = (const float*)d_in[6];
    const float* bet  = (const float*)d_in[7];
    const float* w1   = (const float*)d_in[8];
    const float* w2   = (const float*)d_in[9];
    const float* whc  = (const float*)d_in[10];  // vi_conv_h_w
    const float* wrc  = (const float*)d_in[11];  // vi_conv_r_w
    const float* wqc  = (const float*)d_in[12];  // vi_conv_q_ws (16,10,2,3,3)

    cudaFuncSetAttribute(k_main, cudaFuncAttributeMaxDynamicSharedMemorySize, SMEM_BYTES);

    k_compose<<<1, 256>>>(whf, wrf, whc, wrc);
    k_main<<<N_IMG, 512, SMEM_BYTES>>>(X, S1, S2, wqf, wqc);
    k_epi<<<1, 128>>>(gam, bet, w1, w2, (float*)d_out);
}